// round 5
// baseline (speedup 1.0000x reference)
#include <cuda_runtime.h>
#include <cuda_bf16.h>
#include <cstdint>
#include <math.h>

// ---------------------------------------------------------------------------
// Problem constants
// ---------------------------------------------------------------------------
#define BATCH   2
#define SEQ     2048
#define HID     2048
#define NH      16
#define NKV     4
#define DH      128
#define KVW     (NKV * DH)          // 512
#define MTOT    (BATCH * SEQ)       // 4096
#define GROUPS  (NH / NKV)          // 4
#define GEMM_K  2048
#define NQKV    (HID + 2 * KVW)     // 3072

// ---------------------------------------------------------------------------
// PTX helpers — ONLY non-'a' features (mma.sync / ldmatrix / cp.async).
// ---------------------------------------------------------------------------
__device__ __forceinline__ uint32_t smem_to_u32(const void* p) {
    uint32_t a;
    asm("{ .reg .u64 t; cvta.to.shared.u64 t, %1; cvt.u32.u64 %0, t; }"
        : "=r"(a) : "l"(p));
    return a;
}
#define CP_ASYNC16(dst, src) \
    asm volatile("cp.async.cg.shared.global [%0], [%1], 16;" \
                 :: "r"(dst), "l"(src))
#define CP_ASYNC4(dst, src) \
    asm volatile("cp.async.ca.shared.global [%0], [%1], 4;" \
                 :: "r"(dst), "l"(src))
#define CP_COMMIT() asm volatile("cp.async.commit_group;")
#define CP_WAIT(n)  asm volatile("cp.async.wait_group %0;" :: "n"(n))

__device__ __forceinline__ void ldsm_x4(uint32_t* r, uint32_t addr) {
    asm volatile("ldmatrix.sync.aligned.m8n8.x4.shared.b16 {%0,%1,%2,%3}, [%4];"
                 : "=r"(r[0]), "=r"(r[1]), "=r"(r[2]), "=r"(r[3]) : "r"(addr));
}
__device__ __forceinline__ void mma_bf16(float* d, const uint32_t* a,
                                         const uint32_t* b) {
    asm volatile(
        "mma.sync.aligned.m16n8k16.row.col.f32.bf16.bf16.f32 "
        "{%0,%1,%2,%3}, {%4,%5,%6,%7}, {%8,%9}, {%0,%1,%2,%3};"
        : "+f"(d[0]), "+f"(d[1]), "+f"(d[2]), "+f"(d[3])
        : "r"(a[0]), "r"(a[1]), "r"(a[2]), "r"(a[3]), "r"(b[0]), "r"(b[1]));
}
__device__ __forceinline__ void split2(float x, float y, uint32_t& hi, uint32_t& lo) {
    __nv_bfloat16 bx = __float2bfloat16(x), by = __float2bfloat16(y);
    __nv_bfloat162 h(bx, by);
    hi = *reinterpret_cast<uint32_t*>(&h);
    __nv_bfloat162 l(__float2bfloat16(x - __bfloat162float(bx)),
                     __float2bfloat16(y - __bfloat162float(by)));
    lo = *reinterpret_cast<uint32_t*>(&l);
}

// ---------------------------------------------------------------------------
// Scratch buffers
// ---------------------------------------------------------------------------
__device__ float g_v[(size_t)MTOT * KVW];
__device__ __nv_bfloat16 g_xh[(size_t)MTOT * HID];
__device__ __nv_bfloat16 g_xl[(size_t)MTOT * HID];
__device__ __nv_bfloat16 g_qh[(size_t)MTOT * HID];
__device__ __nv_bfloat16 g_ql[(size_t)MTOT * HID];
__device__ __nv_bfloat16 g_kh[(size_t)MTOT * KVW];
__device__ __nv_bfloat16 g_kl[(size_t)MTOT * KVW];
__device__ __nv_bfloat16 g_vth[(size_t)MTOT * KVW];   // [B*KVW, SEQ]
__device__ __nv_bfloat16 g_vtl[(size_t)MTOT * KVW];
__device__ __nv_bfloat16 g_ah[(size_t)MTOT * HID];
__device__ __nv_bfloat16 g_al[(size_t)MTOT * HID];
__device__ __nv_bfloat16 g_wh[(size_t)NQKV * HID];    // [Wq;Wk;Wv] transposed
__device__ __nv_bfloat16 g_wl[(size_t)NQKV * HID];
__device__ __nv_bfloat16 g_woh[(size_t)HID * HID];
__device__ __nv_bfloat16 g_wol[(size_t)HID * HID];

// ---------------------------------------------------------------------------
// Converters
// ---------------------------------------------------------------------------
__global__ void split_kernel(const float* __restrict__ in,
                             __nv_bfloat16* __restrict__ hi,
                             __nv_bfloat16* __restrict__ lo, int n4)
{
    int i = blockIdx.x * blockDim.x + threadIdx.x;
    if (i >= n4) return;
    float4 v = ((const float4*)in)[i];
    __nv_bfloat16 h0 = __float2bfloat16(v.x);
    __nv_bfloat16 h1 = __float2bfloat16(v.y);
    __nv_bfloat16 h2 = __float2bfloat16(v.z);
    __nv_bfloat16 h3 = __float2bfloat16(v.w);
    ((__nv_bfloat162*)hi)[2*i]   = __nv_bfloat162(h0, h1);
    ((__nv_bfloat162*)hi)[2*i+1] = __nv_bfloat162(h2, h3);
    ((__nv_bfloat162*)lo)[2*i]   = __nv_bfloat162(
        __float2bfloat16(v.x - __bfloat162float(h0)),
        __float2bfloat16(v.y - __bfloat162float(h1)));
    ((__nv_bfloat162*)lo)[2*i+1] = __nv_bfloat162(
        __float2bfloat16(v.z - __bfloat162float(h2)),
        __float2bfloat16(v.w - __bfloat162float(h3)));
}

__global__ void wsplitT_kernel(const float* __restrict__ W,
                               __nv_bfloat16* __restrict__ Th,
                               __nv_bfloat16* __restrict__ Tl,
                               int K, int N)
{
    __shared__ float t[32][33];
    const int n  = blockIdx.x * 32 + threadIdx.x;
    const int kb = blockIdx.y * 32;
    #pragma unroll
    for (int j = 0; j < 32; j += 8)
        t[threadIdx.y + j][threadIdx.x] = W[(size_t)(kb + threadIdx.y + j) * N + n];
    __syncthreads();
    const int k  = kb + threadIdx.x;
    const int nb = blockIdx.x * 32;
    #pragma unroll
    for (int j = 0; j < 32; j += 8) {
        float v = t[threadIdx.x][threadIdx.y + j];
        __nv_bfloat16 h = __float2bfloat16(v);
        size_t o = (size_t)(nb + threadIdx.y + j) * K + k;
        Th[o] = h;
        Tl[o] = __float2bfloat16(v - __bfloat162float(h));
    }
}

__global__ void vsplitT_kernel(const float* __restrict__ V,
                               __nv_bfloat16* __restrict__ Th,
                               __nv_bfloat16* __restrict__ Tl)
{
    __shared__ float t[32][33];
    const int n0 = blockIdx.x * 32;
    const int s0 = blockIdx.y * 32;
    const int b  = blockIdx.z;
    #pragma unroll
    for (int j = 0; j < 32; j += 8)
        t[threadIdx.y + j][threadIdx.x] =
            V[(size_t)(b * SEQ + s0 + threadIdx.y + j) * KVW + n0 + threadIdx.x];
    __syncthreads();
    #pragma unroll
    for (int j = 0; j < 32; j += 8) {
        float v = t[threadIdx.x][threadIdx.y + j];
        __nv_bfloat16 h = __float2bfloat16(v);
        size_t o = (size_t)(b * KVW + n0 + threadIdx.y + j) * SEQ + s0 + threadIdx.x;
        Th[o] = h;
        Tl[o] = __float2bfloat16(v - __bfloat162float(h));
    }
}

// ---------------------------------------------------------------------------
// HMMA GEMM mainloop macro-shared pieces
// ---------------------------------------------------------------------------
#define KC        32
#define AS_STRIDE 40
#define MAT_B     (128 * AS_STRIDE * 2)
#define STAGE_B   (4 * MAT_B)
#define NCHUNK    (GEMM_K / KC)

// Shared mainloop: declares and fills acc[4][4][4]
#define GEMM_MAINLOOP(AhP, AlP, BhP, BlP)                                       \
    float acc[4][4][4];                                                         \
    _Pragma("unroll")                                                           \
    for (int a = 0; a < 4; ++a)                                                 \
        _Pragma("unroll")                                                       \
        for (int b2 = 0; b2 < 4; ++b2)                                          \
            _Pragma("unroll")                                                   \
            for (int c = 0; c < 4; ++c) acc[a][b2][c] = 0.f;                    \
    const __nv_bfloat16* mats[4] = {AhP, AlP, BhP, BlP};                        \
    auto load_stage = [&](int s, int k0) {                                      \
        const uint32_t st = smem_base + s * STAGE_B;                            \
        _Pragma("unroll")                                                       \
        for (int mat = 0; mat < 4; ++mat) {                                     \
            const __nv_bfloat16* src = mats[mat];                               \
            const int r0 = (mat < 2) ? m0 : n0;                                 \
            const uint32_t dstb = st + mat * MAT_B;                             \
            _Pragma("unroll")                                                   \
            for (int it = 0; it < 2; ++it) {                                    \
                const int idx = it * 256 + tid;                                 \
                const int row = idx >> 2;                                       \
                const int k4  = idx & 3;                                        \
                const void* sp = src + (size_t)(r0 + row) * GEMM_K + k0 + k4*8; \
                const uint32_t dp = dstb + row * (AS_STRIDE * 2) + k4 * 16;     \
                CP_ASYNC16(dp, sp);                                             \
            }                                                                   \
        }                                                                       \
    };                                                                          \
    load_stage(0, 0);                                                           \
    CP_COMMIT();                                                                \
    for (int c = 0; c < NCHUNK; ++c) {                                          \
        if (c + 1 < NCHUNK) {                                                   \
            load_stage((c + 1) & 1, (c + 1) * KC);                              \
            CP_COMMIT();                                                        \
            CP_WAIT(1);                                                         \
        } else {                                                                \
            CP_WAIT(0);                                                         \
        }                                                                       \
        __syncthreads();                                                        \
        const uint32_t stg = smem_base + (c & 1) * STAGE_B;                     \
        const uint32_t pAh = stg;                                               \
        const uint32_t pAl = stg + MAT_B;                                       \
        const uint32_t pBh = stg + 2 * MAT_B;                                   \
        const uint32_t pBl = stg + 3 * MAT_B;                                   \
        _Pragma("unroll")                                                       \
        for (int ks = 0; ks < 2; ++ks) {                                        \
            const int kcol = ks * 16;                                           \
            uint32_t bh[8], bl[8];                                              \
            _Pragma("unroll")                                                   \
            for (int p = 0; p < 2; ++p) {                                       \
                const int nrow = wn * 32 + p * 16 + (lane & 7) + ((lane>>4)<<3);\
                const int kk   = kcol + (((lane >> 3) & 1) << 3);               \
                const uint32_t off = (nrow * AS_STRIDE + kk) * 2;               \
                ldsm_x4(&bh[p * 4], pBh + off);                                 \
                ldsm_x4(&bl[p * 4], pBl + off);                                 \
            }                                                                   \
            _Pragma("unroll")                                                   \
            for (int mt = 0; mt < 4; ++mt) {                                    \
                const int mrow = wm * 64 + mt * 16 + (lane & 15);               \
                const int kk2  = kcol + ((lane >> 4) << 3);                     \
                const uint32_t offa = (mrow * AS_STRIDE + kk2) * 2;             \
                uint32_t afr[4];                                                \
                ldsm_x4(afr, pAh + offa);                                       \
                _Pragma("unroll")                                               \
                for (int nt = 0; nt < 4; ++nt) mma_bf16(acc[mt][nt], afr, &bh[nt*2]); \
                _Pragma("unroll")                                               \
                for (int nt = 0; nt < 4; ++nt) mma_bf16(acc[mt][nt], afr, &bl[nt*2]); \
                ldsm_x4(afr, pAl + offa);                                       \
                _Pragma("unroll")                                               \
                for (int nt = 0; nt < 4; ++nt) mma_bf16(acc[mt][nt], afr, &bh[nt*2]); \
            }                                                                   \
        }                                                                       \
        __syncthreads();                                                        \
    }

// ---------------------------------------------------------------------------
// Fused QKV projection GEMM: N = 3072 (q 0:2048 split, k 2048:2560 split,
// v 2560:3072 fp32)
// ---------------------------------------------------------------------------
__global__ void __launch_bounds__(256)
gemm_qkv(const __nv_bfloat16* __restrict__ Ah, const __nv_bfloat16* __restrict__ Al,
         const __nv_bfloat16* __restrict__ Bh, const __nv_bfloat16* __restrict__ Bl,
         const float* __restrict__ bq, const float* __restrict__ bk,
         const float* __restrict__ bv,
         __nv_bfloat16* __restrict__ Qh, __nv_bfloat16* __restrict__ Ql,
         __nv_bfloat16* __restrict__ Kh, __nv_bfloat16* __restrict__ Kl,
         float* __restrict__ Vo)
{
    extern __shared__ __align__(128) char smem[];
    const uint32_t smem_base = smem_to_u32(smem);
    const int tid  = threadIdx.x;
    const int warp = tid >> 5;
    const int lane = tid & 31;
    const int wm   = warp >> 2;
    const int wn   = warp & 3;
    const int m0   = blockIdx.y * 128;
    const int n0   = blockIdx.x * 128;

    GEMM_MAINLOOP(Ah, Al, Bh, Bl)

    #pragma unroll
    for (int mt = 0; mt < 4; ++mt)
        #pragma unroll
        for (int rh = 0; rh < 2; ++rh) {
            const int row = m0 + wm * 64 + mt * 16 + (lane >> 2) + rh * 8;
            #pragma unroll
            for (int nt = 0; nt < 4; ++nt) {
                const int col = n0 + wn * 32 + nt * 8 + (lane & 3) * 2;
                if (n0 < HID) {
                    const float v0 = acc[mt][nt][rh*2+0] + bq[col];
                    const float v1 = acc[mt][nt][rh*2+1] + bq[col+1];
                    uint32_t hi, lo;
                    split2(v0, v1, hi, lo);
                    *(uint32_t*)&Qh[(size_t)row * HID + col] = hi;
                    *(uint32_t*)&Ql[(size_t)row * HID + col] = lo;
                } else if (n0 < HID + KVW) {
                    const int c2 = col - HID;
                    const float v0 = acc[mt][nt][rh*2+0] + bk[c2];
                    const float v1 = acc[mt][nt][rh*2+1] + bk[c2+1];
                    uint32_t hi, lo;
                    split2(v0, v1, hi, lo);
                    *(uint32_t*)&Kh[(size_t)row * KVW + c2] = hi;
                    *(uint32_t*)&Kl[(size_t)row * KVW + c2] = lo;
                } else {
                    const int c2 = col - HID - KVW;
                    float2 v;
                    v.x = acc[mt][nt][rh*2+0] + bv[c2];
                    v.y = acc[mt][nt][rh*2+1] + bv[c2+1];
                    *(float2*)&Vo[(size_t)row * KVW + c2] = v;
                }
            }
        }
}

// ---------------------------------------------------------------------------
// O-projection GEMM (fp32 out)
// ---------------------------------------------------------------------------
__global__ void __launch_bounds__(256)
gemm_o(const __nv_bfloat16* __restrict__ Ah, const __nv_bfloat16* __restrict__ Al,
       const __nv_bfloat16* __restrict__ Bh, const __nv_bfloat16* __restrict__ Bl,
       const float* __restrict__ bias, float* __restrict__ C)
{
    extern __shared__ __align__(128) char smem[];
    const uint32_t smem_base = smem_to_u32(smem);
    const int tid  = threadIdx.x;
    const int warp = tid >> 5;
    const int lane = tid & 31;
    const int wm   = warp >> 2;
    const int wn   = warp & 3;
    const int m0   = blockIdx.y * 128;
    const int n0   = blockIdx.x * 128;

    GEMM_MAINLOOP(Ah, Al, Bh, Bl)

    #pragma unroll
    for (int mt = 0; mt < 4; ++mt)
        #pragma unroll
        for (int rh = 0; rh < 2; ++rh) {
            const int row = m0 + wm * 64 + mt * 16 + (lane >> 2) + rh * 8;
            #pragma unroll
            for (int nt = 0; nt < 4; ++nt) {
                const int col = n0 + wn * 32 + nt * 8 + (lane & 3) * 2;
                float2 v;
                v.x = acc[mt][nt][rh*2+0] + bias[col];
                v.y = acc[mt][nt][rh*2+1] + bias[col+1];
                *(float2*)&C[(size_t)row * HID + col] = v;
            }
        }
}

// ---------------------------------------------------------------------------
// HMMA FlashAttention: 128 q-rows x 128 kv tiles, 8 warps (16 q-rows each).
// ---------------------------------------------------------------------------
#define QSTR 136
#define SM_QH 0
#define SM_QL 34816
#define SM_KH 69632
#define SM_KL 104448
#define SM_VH 139264
#define SM_VL 174080
#define SM_MK 208896
#define ATTN_SMEM 209408

__global__ void __launch_bounds__(256)
attn_hmma(const __nv_bfloat16* __restrict__ Qh, const __nv_bfloat16* __restrict__ Ql,
          const __nv_bfloat16* __restrict__ Kh, const __nv_bfloat16* __restrict__ Kl,
          const __nv_bfloat16* __restrict__ VTh, const __nv_bfloat16* __restrict__ VTl,
          const int* __restrict__ mask,
          __nv_bfloat16* __restrict__ OH, __nv_bfloat16* __restrict__ OL)
{
    extern __shared__ __align__(128) char sm[];
    const uint32_t base = smem_to_u32(sm);
    const int tid = threadIdx.x;
    const int w    = tid >> 5;
    const int lane = tid & 31;
    // reversed qb: heavy blocks launch first (load balance over 3.46 waves)
    const int qb = (int)gridDim.x - 1 - (int)blockIdx.x;
    const int h = blockIdx.y, b = blockIdx.z;
    const int q0 = qb * 128;
    const int kvh = h >> 2;
    const int T = qb + 1;
    const float scl = 0.08838834764831845f;

    auto load_k = [&](int k0) {
        #pragma unroll
        for (int mat = 0; mat < 2; ++mat) {
            const __nv_bfloat16* src = mat ? Kl : Kh;
            const uint32_t dst = base + (mat ? SM_KL : SM_KH);
            #pragma unroll
            for (int i = 0; i < 8; ++i) {
                const int idx = i * 256 + tid;
                const int row = idx >> 4, c = idx & 15;
                CP_ASYNC16(dst + row * 272 + c * 16,
                           src + (size_t)(b * SEQ + k0 + row) * KVW + kvh * DH + c * 8);
            }
        }
        if (tid < 128)
            CP_ASYNC4(base + SM_MK + tid * 4, mask + b * SEQ + k0 + tid);
    };
    auto load_v = [&](int k0) {
        #pragma unroll
        for (int mat = 0; mat < 2; ++mat) {
            const __nv_bfloat16* src = mat ? VTl : VTh;
            const uint32_t dst = base + (mat ? SM_VL : SM_VH);
            #pragma unroll
            for (int i = 0; i < 8; ++i) {
                const int idx = i * 256 + tid;
                const int row = idx >> 4, c = idx & 15;
                CP_ASYNC16(dst + row * 272 + c * 16,
                           src + (size_t)(b * KVW + kvh * DH + row) * SEQ + k0 + c * 8);
            }
        }
    };

    // prologue: Q + K(0) + mask(0)
    #pragma unroll
    for (int mat = 0; mat < 2; ++mat) {
        const __nv_bfloat16* src = mat ? Ql : Qh;
        const uint32_t dst = base + (mat ? SM_QL : SM_QH);
        #pragma unroll
        for (int i = 0; i < 8; ++i) {
            const int idx = i * 256 + tid;
            const int row = idx >> 4, c = idx & 15;
            CP_ASYNC16(dst + row * 272 + c * 16,
                       src + (size_t)(b * SEQ + q0 + row) * HID + h * DH + c * 8);
        }
    }
    load_k(0);
    CP_COMMIT();
    CP_WAIT(0);
    __syncthreads();

    float o[16][4];
    #pragma unroll
    for (int j = 0; j < 16; ++j)
        #pragma unroll
        for (int c = 0; c < 4; ++c) o[j][c] = 0.f;
    float m0 = -1e30f, m1 = -1e30f, l0 = 0.f, l1 = 0.f;

    const int r0g = q0 + w * 16 + (lane >> 2);
    const int r1g = r0g + 8;
    const int c0l = (lane & 3) * 2;
    const int* mk_s = (const int*)(sm + SM_MK);

    for (int t = 0; t < T; ++t) {
        const int k0 = t * 128;

        load_v(k0);
        CP_COMMIT();

        float s[16][4];
        #pragma unroll
        for (int j = 0; j < 16; ++j)
            #pragma unroll
            for (int c = 0; c < 4; ++c) s[j][c] = 0.f;

        // S = Qh*Kh + Qh*Kl + Ql*Kh
        #pragma unroll
        for (int kc = 0; kc < 8; ++kc) {
            const uint32_t offa =
                ((w * 16 + (lane & 15)) * QSTR + kc * 16 + ((lane >> 4) << 3)) * 2;
            uint32_t ah[4], al[4];
            ldsm_x4(ah, base + SM_QH + offa);
            ldsm_x4(al, base + SM_QL + offa);
            #pragma unroll
            for (int g = 0; g < 8; ++g) {
                const uint32_t offb =
                    ((g * 16 + (lane & 7) + ((lane >> 4) << 3)) * QSTR +
                     kc * 16 + (((lane >> 3) & 1) << 3)) * 2;
                uint32_t bh[4], bl[4];
                ldsm_x4(bh, base + SM_KH + offb);
                ldsm_x4(bl, base + SM_KL + offb);
                mma_bf16(s[2*g],   ah, &bh[0]);
                mma_bf16(s[2*g+1], ah, &bh[2]);
                mma_bf16(s[2*g],   ah, &bl[0]);
                mma_bf16(s[2*g+1], ah, &bl[2]);
                mma_bf16(s[2*g],   al, &bh[0]);
                mma_bf16(s[2*g+1], al, &bh[2]);
            }
        }

        // mask + scale + online softmax (registers)
        float mx0 = -1e30f, mx1 = -1e30f;
        #pragma unroll
        for (int j = 0; j < 16; ++j) {
            const int cg = k0 + j * 8 + c0l;
            const int mk0 = mk_s[j * 8 + c0l];
            const int mk1 = mk_s[j * 8 + c0l + 1];
            s[j][0] = (cg     <= r0g && mk0) ? s[j][0] * scl : -1e30f;
            s[j][1] = (cg + 1 <= r0g && mk1) ? s[j][1] * scl : -1e30f;
            s[j][2] = (cg     <= r1g && mk0) ? s[j][2] * scl : -1e30f;
            s[j][3] = (cg + 1 <= r1g && mk1) ? s[j][3] * scl : -1e30f;
            mx0 = fmaxf(mx0, fmaxf(s[j][0], s[j][1]));
            mx1 = fmaxf(mx1, fmaxf(s[j][2], s[j][3]));
        }
        mx0 = fmaxf(mx0, __shfl_xor_sync(0xffffffff, mx0, 1));
        mx0 = fmaxf(mx0, __shfl_xor_sync(0xffffffff, mx0, 2));
        mx1 = fmaxf(mx1, __shfl_xor_sync(0xffffffff, mx1, 1));
        mx1 = fmaxf(mx1, __shfl_xor_sync(0xffffffff, mx1, 2));
        const float mn0 = fmaxf(m0, mx0), mn1 = fmaxf(m1, mx1);
        const float f0 = __expf(m0 - mn0), f1 = __expf(m1 - mn1);
        m0 = mn0; m1 = mn1;
        float sum0 = 0.f, sum1 = 0.f;
        #pragma unroll
        for (int j = 0; j < 16; ++j) {
            s[j][0] = __expf(s[j][0] - mn0);
            s[j][1] = __expf(s[j][1] - mn0);
            s[j][2] = __expf(s[j][2] - mn1);
            s[j][3] = __expf(s[j][3] - mn1);
            sum0 += s[j][0] + s[j][1];
            sum1 += s[j][2] + s[j][3];
        }
        sum0 += __shfl_xor_sync(0xffffffff, sum0, 1);
        sum0 += __shfl_xor_sync(0xffffffff, sum0, 2);
        sum1 += __shfl_xor_sync(0xffffffff, sum1, 1);
        sum1 += __shfl_xor_sync(0xffffffff, sum1, 2);
        l0 = l0 * f0 + sum0;
        l1 = l1 * f1 + sum1;
        #pragma unroll
        for (int j = 0; j < 16; ++j) {
            o[j][0] *= f0; o[j][1] *= f0;
            o[j][2] *= f1; o[j][3] *= f1;
        }

        CP_WAIT(0);            // VT(t) ready
        __syncthreads();       // all warps done reading K(t)
        if (t + 1 < T) {
            load_k(k0 + 128);
            CP_COMMIT();
        }

        // O += Ph*Vh + Ph*Vl + Pl*Vh
        #pragma unroll
        for (int kc = 0; kc < 8; ++kc) {
            uint32_t aph[4], apl[4];
            split2(s[2*kc][0],   s[2*kc][1],   aph[0], apl[0]);
            split2(s[2*kc][2],   s[2*kc][3],   aph[1], apl[1]);
            split2(s[2*kc+1][0], s[2*kc+1][1], aph[2], apl[2]);
            split2(s[2*kc+1][2], s[2*kc+1][3], aph[3], apl[3]);
            #pragma unroll
            for (int g = 0; g < 8; ++g) {
                const uint32_t offb =
                    ((g * 16 + (lane & 7) + ((lane >> 4) << 3)) * QSTR +
                     kc * 16 + (((lane >> 3) & 1) << 3)) * 2;
                uint32_t bh[4], bl[4];
                ldsm_x4(bh, base + SM_VH + offb);
                ldsm_x4(bl, base + SM_VL + offb);
                mma_bf16(o[2*g],   aph, &bh[0]);
                mma_bf16(o[2*g+1], aph, &bh[2]);
                mma_bf16(o[2*g],   aph, &bl[0]);
                mma_bf16(o[2*g+1], aph, &bl[2]);
                mma_bf16(o[2*g],   apl, &bh[0]);
                mma_bf16(o[2*g+1], apl, &bh[2]);
            }
        }

        CP_WAIT(0);            // K(t+1) ready
        __syncthreads();       // all warps done reading V(t)
    }

    // epilogue: normalize, split bf16 hi/lo, store
    const float inv0 = 1.f / l0, inv1 = 1.f / l1;
    const size_t base0 = (size_t)(b * SEQ + r0g) * HID + h * DH;
    const size_t base1 = (size_t)(b * SEQ + r1g) * HID + h * DH;
    #pragma unroll
    for (int j = 0; j < 16; ++j) {
        const int col = j * 8 + c0l;
        uint32_t hi, lo;
        split2(o[j][0] * inv0, o[j][1] * inv0, hi, lo);
        *(uint32_t*)&OH[base0 + col] = hi;
        *(uint32_t*)&OL[base0 + col] = lo;
        split2(o[j][2] * inv1, o[j][3] * inv1, hi, lo);
        *(uint32_t*)&OH[base1 + col] = hi;
        *(uint32_t*)&OL[base1 + col] = lo;
    }
}

// ---------------------------------------------------------------------------
// Launch
// ---------------------------------------------------------------------------
extern "C" void kernel_launch(void* const* d_in, const int* in_sizes, int n_in,
                              void* d_out, int out_size)
{
    const float* x    = (const float*)d_in[0];
    const int*   mask = (const int*)  d_in[1];
    const float* Wq   = (const float*)d_in[2];
    const float* bq   = (const float*)d_in[3];
    const float* Wk   = (const float*)d_in[4];
    const float* bk   = (const float*)d_in[5];
    const float* Wv   = (const float*)d_in[6];
    const float* bv   = (const float*)d_in[7];
    const float* Wo   = (const float*)d_in[8];
    const float* bo   = (const float*)d_in[9];
    float* out = (float*)d_out;

    void *pv, *pxh, *pxl, *pqh, *pql, *pkh, *pkl, *pvth, *pvtl, *pah, *pal;
    void *pwh, *pwl, *pwoh, *pwol;
    cudaGetSymbolAddress(&pv,  g_v);
    cudaGetSymbolAddress(&pxh, g_xh);  cudaGetSymbolAddress(&pxl, g_xl);
    cudaGetSymbolAddress(&pqh, g_qh);  cudaGetSymbolAddress(&pql, g_ql);
    cudaGetSymbolAddress(&pkh, g_kh);  cudaGetSymbolAddress(&pkl, g_kl);
    cudaGetSymbolAddress(&pvth, g_vth); cudaGetSymbolAddress(&pvtl, g_vtl);
    cudaGetSymbolAddress(&pah, g_ah);  cudaGetSymbolAddress(&pal, g_al);
    cudaGetSymbolAddress(&pwh, g_wh);  cudaGetSymbolAddress(&pwl, g_wl);
    cudaGetSymbolAddress(&pwoh, g_woh); cudaGetSymbolAddress(&pwol, g_wol);

    __nv_bfloat16* wh = (__nv_bfloat16*)pwh;
    __nv_bfloat16* wl = (__nv_bfloat16*)pwl;

    // --- converters ---
    const int n4 = MTOT * HID / 4;
    split_kernel<<<n4 / 256, 256>>>(x, (__nv_bfloat16*)pxh, (__nv_bfloat16*)pxl, n4);
    dim3 tb(32, 8);
    wsplitT_kernel<<<dim3(HID / 32, HID / 32), tb>>>(Wq, wh, wl, HID, HID);
    wsplitT_kernel<<<dim3(KVW / 32, HID / 32), tb>>>(
        Wk, wh + (size_t)HID * HID, wl + (size_t)HID * HID, HID, KVW);
    wsplitT_kernel<<<dim3(KVW / 32, HID / 32), tb>>>(
        Wv, wh + (size_t)(HID + KVW) * HID, wl + (size_t)(HID + KVW) * HID, HID, KVW);
    wsplitT_kernel<<<dim3(HID / 32, HID / 32), tb>>>(Wo, (__nv_bfloat16*)pwoh,
                                                     (__nv_bfloat16*)pwol, HID, HID);

    // --- fused QKV projection ---
    const int gemm_smem = 2 * STAGE_B;
    cudaFuncSetAttribute(gemm_qkv, cudaFuncAttributeMaxDynamicSharedMemorySize,
                         gemm_smem);
    cudaFuncSetAttribute(gemm_o, cudaFuncAttributeMaxDynamicSharedMemorySize,
                         gemm_smem);
    gemm_qkv<<<dim3(NQKV / 128, MTOT / 128), 256, gemm_smem>>>(
        (const __nv_bfloat16*)pxh, (const __nv_bfloat16*)pxl, wh, wl,
        bq, bk, bv,
        (__nv_bfloat16*)pqh, (__nv_bfloat16*)pql,
        (__nv_bfloat16*)pkh, (__nv_bfloat16*)pkl, (float*)pv);

    // --- V transpose + split ---
    vsplitT_kernel<<<dim3(KVW / 32, SEQ / 32, BATCH), tb>>>(
        (const float*)pv, (__nv_bfloat16*)pvth, (__nv_bfloat16*)pvtl);

    // --- HMMA flash attention (128-wide kv tiles, reversed schedule) ---
    cudaFuncSetAttribute(attn_hmma, cudaFuncAttributeMaxDynamicSharedMemorySize,
                         ATTN_SMEM);
    attn_hmma<<<dim3(SEQ / 128, NH, BATCH), 256, ATTN_SMEM>>>(
        (const __nv_bfloat16*)pqh, (const __nv_bfloat16*)pql,
        (const __nv_bfloat16*)pkh, (const __nv_bfloat16*)pkl,
        (const __nv_bfloat16*)pvth, (const __nv_bfloat16*)pvtl,
        mask, (__nv_bfloat16*)pah, (__nv_bfloat16*)pal);

    // --- output projection ---
    gemm_o<<<dim3(HID / 128, MTOT / 128), 256, gemm_smem>>>(
        (const __nv_bfloat16*)pah, (const __nv_bfloat16*)pal,
        (const __nv_bfloat16*)pwoh, (const __nv_bfloat16*)pwol, bo, out);
}